// round 11
// baseline (speedup 1.0000x reference)
#include <cuda_runtime.h>
#include <cuda_bf16.h>

#define NB 32
#define NS 1024
#define ND 256

typedef unsigned long long ull;

// ---------------- packed f32x2 helpers --------------------------------------
__device__ __forceinline__ void FMA2(ull& d, ull a, ull b) {
    asm("fma.rn.f32x2 %0, %1, %2, %0;" : "+l"(d) : "l"(a), "l"(b));
}
__device__ __forceinline__ ull MUL2(ull a, ull b) {
    ull d;
    asm("mul.rn.f32x2 %0, %1, %2;" : "=l"(d) : "l"(a), "l"(b));
    return d;
}
__device__ __forceinline__ ull splat2(float v) {
    ull r;
    asm("mov.b64 %0, {%1, %1};" : "=l"(r) : "f"(v));
    return r;
}
__device__ __forceinline__ ull pack2(float x, float y) {
    ull r;
    asm("mov.b64 %0, {%1, %2};" : "=l"(r) : "f"(x), "f"(y));
    return r;
}
__device__ __forceinline__ float2 u2f(ull v) {
    float2 r;
    asm("mov.b64 {%0, %1}, %2;" : "=f"(r.x), "=f"(r.y) : "l"(v));
    return r;
}

// ---------------- scratch (static __device__, no allocation) ----------------
__device__ __align__(16) float g_M[ND][ND];     // M[d][e] = sum_a Wq[a][d]*Wk[a][e]
__device__ __align__(16) float g_vecA[ND];      // Wq^T bk
__device__ __align__(16) float g_vecB[ND];      // Wk^T bq
__device__ float g_c;                           // bq . bk
__device__ int   g_sw_idx[NB][NS];
__device__ int   g_dr_idx[NB][NS];
__device__ int   g_nsw[NB];
__device__ int   g_ndr[NB];
__device__ int   g_swf[NB * NS];                // 1 iff switch row
__device__ __align__(16) float g_partAll[NB][4][ND];
__device__ __align__(16) float g_partDoor[NB][4][ND];
__device__ __align__(16) float g_z[NB][NS][ND]; // cw*(x_s . M) per switch slot

// ---------------- K_M: M = Wq^T Wk (32x32 tiles) + bias vectors + c ---------
__global__ void __launch_bounds__(256) k_M(const float* __restrict__ Wq,
                                           const float* __restrict__ Wk,
                                           const float* __restrict__ bq,
                                           const float* __restrict__ bk) {
    int tid = threadIdx.x;
    if (blockIdx.x == 64) {
        int d = tid;
        float va = 0.f, vb = 0.f;
        #pragma unroll 8
        for (int a = 0; a < ND; a++) {
            va += Wq[a * ND + d] * bk[a];
            vb += Wk[a * ND + d] * bq[a];
        }
        g_vecA[d] = va;
        g_vecB[d] = vb;
        if (tid < 32) {
            float c = 0.f;
            for (int i = tid; i < ND; i += 32) c += bq[i] * bk[i];
            #pragma unroll
            for (int o = 16; o; o >>= 1) c += __shfl_down_sync(0xFFFFFFFFu, c, o);
            if (tid == 0) g_c = c;
        }
        return;
    }
    int dt = blockIdx.x >> 3, et = blockIdx.x & 7;
    __shared__ float As[16][32], Bs[16][32];
    float a00 = 0.f, a01 = 0.f, a10 = 0.f, a11 = 0.f;
    int dg = tid >> 4, eg = tid & 15;
    int al = tid >> 4, c2 = (tid & 15) * 2;
    for (int a0 = 0; a0 < ND; a0 += 16) {
        *(float2*)&As[al][c2] = *(const float2*)&Wq[(a0 + al) * ND + dt * 32 + c2];
        *(float2*)&Bs[al][c2] = *(const float2*)&Wk[(a0 + al) * ND + et * 32 + c2];
        __syncthreads();
        #pragma unroll
        for (int k = 0; k < 16; k++) {
            float2 av = *(const float2*)&As[k][dg * 2];
            float2 bv = *(const float2*)&Bs[k][eg * 2];
            a00 += av.x * bv.x; a01 += av.x * bv.y;
            a10 += av.y * bv.x; a11 += av.y * bv.y;
        }
        __syncthreads();
    }
    int d = dt * 32 + dg * 2, e = et * 32 + eg * 2;
    g_M[d][e]     = a00; g_M[d][e + 1]     = a01;
    g_M[d + 1][e] = a10; g_M[d + 1][e + 1] = a11;
}

// ---------------- K_prep2: dtype detect + masks/flags (bz0) | colsum --------
__global__ void __launch_bounds__(1024) k_prep2(const int* __restrict__ s32,
                                                const float* __restrict__ emb) {
    int b = blockIdx.x, bz = blockIdx.y, tid = threadIdx.x;
    int vdet = (tid < 512) ? s32[b * NS + 2 * tid + 1] : 0;
    int is64 = !__syncthreads_or(vdet != 0);

    if (bz == 0) {
        int t = tid;
        int st = is64 ? s32[2 * (b * NS + t)] : s32[b * NS + t];
        int isw = (st == 3), idr = (st == 4 || st == 5);
        g_swf[b * NS + t] = isw;
        unsigned mw = __ballot_sync(0xFFFFFFFFu, isw);
        unsigned md = __ballot_sync(0xFFFFFFFFu, idr);
        int lane = t & 31, w = t >> 5;
        __shared__ int cw_[32], cd_[32], ow_[32], od_[32];
        if (lane == 0) { cw_[w] = __popc(mw); cd_[w] = __popc(md); }
        __syncthreads();
        if (tid == 0) {
            int aw = 0, ad = 0;
            for (int i = 0; i < 32; i++) {
                ow_[i] = aw; aw += cw_[i];
                od_[i] = ad; ad += cd_[i];
            }
            g_nsw[b] = aw; g_ndr[b] = ad;
        }
        __syncthreads();
        if (isw) g_sw_idx[b][ow_[w] + __popc(mw & ((1u << lane) - 1u))] = t;
        if (idr) g_dr_idx[b][od_[w] + __popc(md & ((1u << lane) - 1u))] = t;
    } else {
        int c = bz - 1, tg = tid >> 8, d = tid & 255;
        float sa = 0.f, sd = 0.f;
        int tb = c * 256 + tg * 64;
        #pragma unroll 4
        for (int i = 0; i < 64; i++) {
            int t = tb + i;
            float v = emb[((size_t)b * NS + t) * ND + d];
            int st = is64 ? s32[2 * (b * NS + t)] : s32[b * NS + t];
            sa += v;
            if (st == 4 || st == 5) sd += v;
        }
        __shared__ float psA[4][ND], psD[4][ND];
        psA[tg][d] = sa; psD[tg][d] = sd;
        __syncthreads();
        if (tid < ND) {
            float a = 0.f, dd = 0.f;
            #pragma unroll
            for (int g = 0; g < 4; g++) { a += psA[g][tid]; dd += psD[g][tid]; }
            g_partAll[b][c][tid]  = a;
            g_partDoor[b][c][tid] = dd;
        }
    }
}

// ---------------- K_default: out = emb + 0.5*colMean (non-switch rows only) -
__global__ void __launch_bounds__(256) k_default(const float* __restrict__ emb,
                                                 float* __restrict__ out) {
    size_t e4 = (size_t)blockIdx.x * 256 + threadIdx.x;
    int row = (int)(e4 >> 6);               // b*NS + s
    if (g_swf[row]) return;                  // switch rows owned by k_attn
    int b  = (int)(e4 >> 16);
    int d4 = (int)(e4 & 63);
    float4 p0 = ((const float4*)g_partAll[b][0])[d4];
    float4 p1 = ((const float4*)g_partAll[b][1])[d4];
    float4 p2 = ((const float4*)g_partAll[b][2])[d4];
    float4 p3 = ((const float4*)g_partAll[b][3])[d4];
    const float kk = 0.5f / 1024.f;
    float4 v = ((const float4*)emb)[e4];
    v.x += (p0.x + p1.x + p2.x + p3.x) * kk;
    v.y += (p0.y + p1.y + p2.y + p3.y) * kk;
    v.z += (p0.z + p1.z + p2.z + p3.z) * kk;
    v.w += (p0.w + p1.w + p2.w + p3.w) * kk;
    ((float4*)out)[e4] = v;
}

// ---------------- K_z: z = cw * X_switch . M, 32x128 reg tiles --------------
// 32-row tiles -> 2x live blocks vs 64-row version (occupancy/latency fix).
__global__ void __launch_bounds__(256) k_z(const float* __restrict__ emb,
                                           const float* __restrict__ cwp) {
    int et = blockIdx.x, b = blockIdx.y, mt = blockIdx.z;
    int nsw = g_nsw[b];
    if (mt * 32 >= nsw) return;
    int tid = threadIdx.x;
    __shared__ float Xs[2][16][36];
    __shared__ float Ms[2][16][132];
    __shared__ const float* rp[32];
    if (tid < 32) {
        int slot = mt * 32 + tid;
        rp[tid] = emb + ((size_t)b * NS + g_sw_idx[b][min(slot, nsw - 1)]) * ND;
    }
    __syncthreads();
    const int xrow = tid >> 3, xk2 = (tid & 7) * 2;   // X: 32 rows x 2 k-floats
    const int mkr = tid >> 5,  me4 = (tid & 31) * 4;  // M: k rows mkr,mkr+8 x 4 e
    const int rg = tid >> 4, eg = tid & 15;           // out: rows rg*2.., e eg*8..
    const float* xp = rp[xrow];
    const float* mp = &g_M[0][et * 128 + me4];

    float2 xv = *(const float2*)(xp + xk2);
    float4 ma = *(const float4*)(mp + (size_t)mkr * ND);
    float4 mb = *(const float4*)(mp + (size_t)(mkr + 8) * ND);
    Xs[0][xk2 + 0][xrow] = xv.x; Xs[0][xk2 + 1][xrow] = xv.y;
    *(float4*)&Ms[0][mkr][me4]     = ma;
    *(float4*)&Ms[0][mkr + 8][me4] = mb;
    __syncthreads();

    ull acc[2][4];
    #pragma unroll
    for (int r = 0; r < 2; r++)
        #pragma unroll
        for (int p = 0; p < 4; p++) acc[r][p] = 0ULL;

    for (int s = 0; s < 16; s++) {
        int cur = s & 1;
        if (s + 1 < 16) {
            int k0 = (s + 1) * 16;
            xv = *(const float2*)(xp + k0 + xk2);
            ma = *(const float4*)(mp + (size_t)(k0 + mkr) * ND);
            mb = *(const float4*)(mp + (size_t)(k0 + mkr + 8) * ND);
        }
        #pragma unroll
        for (int k = 0; k < 16; k++) {
            float2 xf = *(const float2*)&Xs[cur][k][rg * 2];
            ulonglong2 m0 = *(const ulonglong2*)&Ms[cur][k][eg * 8];
            ulonglong2 m1 = *(const ulonglong2*)&Ms[cur][k][eg * 8 + 4];
            ull x0 = splat2(xf.x), x1 = splat2(xf.y);
            FMA2(acc[0][0], x0, m0.x); FMA2(acc[0][1], x0, m0.y);
            FMA2(acc[0][2], x0, m1.x); FMA2(acc[0][3], x0, m1.y);
            FMA2(acc[1][0], x1, m0.x); FMA2(acc[1][1], x1, m0.y);
            FMA2(acc[1][2], x1, m1.x); FMA2(acc[1][3], x1, m1.y);
        }
        if (s + 1 < 16) {
            int nb2 = cur ^ 1;
            Xs[nb2][xk2 + 0][xrow] = xv.x; Xs[nb2][xk2 + 1][xrow] = xv.y;
            *(float4*)&Ms[nb2][mkr][me4]     = ma;
            *(float4*)&Ms[nb2][mkr + 8][me4] = mb;
            __syncthreads();
        }
    }
    float cwv = *cwp;
    #pragma unroll
    for (int r = 0; r < 2; r++) {
        int slot = mt * 32 + rg * 2 + r;
        if (slot < nsw) {
            float2 a0 = u2f(acc[r][0]), a1 = u2f(acc[r][1]);
            float2 a2 = u2f(acc[r][2]), a3 = u2f(acc[r][3]);
            float4 o0 = make_float4(cwv * a0.x, cwv * a0.y, cwv * a1.x, cwv * a1.y);
            float4 o1 = make_float4(cwv * a2.x, cwv * a2.y, cwv * a3.x, cwv * a3.y);
            *(float4*)&g_z[b][slot][et * 128 + eg * 8]     = o0;
            *(float4*)&g_z[b][slot][et * 128 + eg * 8 + 4] = o1;
        }
    }
}

// ---------------- K_attn: fused, 512 thr, 32i x 128j, K-split score GEMM ----
// eh = tid>>8 selects e-half for scores (partials combined via ssh) and
// i-half for the V accumulation. Same crossbar/FMA totals, 2x warps/SMSP.
struct AttnSmem {
    float Esh[128][260];   // door-row emb tile (pad: phase-conflict-free)
    float zsh[32][260];    // z rows for this i-tile
    float ssh[128][36];    // half1 partial scores -> softmax weights [j][i]
    float red[32][36];     // per-jg partial max/sum [jg][i]
    float uch[128];
    int   tj[128];
    float vch[32];
    float m[32];
    float dsum[32];
    float scale[32];
    float vA[ND];
    float vB[ND];
};

__global__ void __launch_bounds__(512) k_attn(const float* __restrict__ emb,
                                              float* __restrict__ out,
                                              const float* __restrict__ cwp) {
    extern __shared__ char smraw[];
    AttnSmem* S = (AttnSmem*)smraw;
    const int mt = blockIdx.x, b = blockIdx.y;
    const int nsw = g_nsw[b];
    const int i0 = mt * 32;
    if (i0 >= nsw) return;
    const int nd = g_ndr[b];
    const int tid = threadIdx.x;
    const int ni = min(32, nsw - i0);
    const float cwv = *cwp;

    // ---- prologue: z tile, bias vectors, m/dsum, vc
    for (int idx = tid; idx < 32 * 64; idx += 512) {
        int i = idx >> 6, q = idx & 63;
        float4 v = (i < ni) ? ((const float4*)&g_z[b][i0 + i][0])[q]
                            : make_float4(0.f, 0.f, 0.f, 0.f);
        *(float4*)&S->zsh[i][q * 4] = v;
    }
    if (tid < ND) { S->vA[tid] = g_vecA[tid]; S->vB[tid] = g_vecB[tid]; }
    if (tid < 32) {
        S->m[tid]    = (nd < NS) ? 0.f : -1e30f;
        S->dsum[tid] = 0.f;
    }
    {   // vc: warp w (0..15) covers rows w, w+16
        int w = tid >> 5, lane = tid & 31;
        for (int r = w; r < 32; r += 16) {
            float val = -1e30f;
            if (r < ni) {
                int srow = g_sw_idx[b][i0 + r];
                const float4* er = (const float4*)&emb[((size_t)b * NS + srow) * ND];
                const float4* vr = (const float4*)g_vecA;
                float s = 0.f;
                #pragma unroll
                for (int j2 = 0; j2 < 2; j2++) {
                    float4 e4 = er[lane + 32 * j2], v4 = vr[lane + 32 * j2];
                    s += e4.x * v4.x + e4.y * v4.y + e4.z * v4.z + e4.w * v4.w;
                }
                #pragma unroll
                for (int o = 16; o; o >>= 1) s += __shfl_down_sync(0xFFFFFFFFu, s, o);
                val = cwv * (s + g_c);
            }
            if (lane == 0) S->vch[r] = val;
        }
    }

    const int eh = tid >> 8;         // 0/1: e-half (scores), i-half (V)
    const int t8 = tid & 255;
    const int ig = t8 >> 5;          // 0..7  -> i = ig*4 + r
    const int jg = t8 & 31;          // 0..31 -> j = jg + 32*c
    const int e0 = eh * 128;
    const int ih = eh * 16;          // V-phase i-half base
    const int dd = t8;               // V-phase d index

    ull accv[8];
    #pragma unroll
    for (int p = 0; p < 8; p++) accv[p] = 0ULL;

    for (int jb = 0; jb < nd; jb += 128) {
        int cnt = min(128, nd - jb);
        __syncthreads();
        if (tid < 128)
            S->tj[tid] = g_dr_idx[b][(tid < cnt) ? (jb + tid) : jb];
        __syncthreads();
        for (int idx = tid; idx < 128 * 64; idx += 512) {
            int j = idx >> 6, q = idx & 63;
            float4 v = ((const float4*)&emb[((size_t)b * NS + S->tj[j]) * ND])[q];
            *(float4*)&S->Esh[j][q * 4] = v;
        }
        __syncthreads();
        // ---- uc_j = cw * (E_j . vecB): 4 threads per j
        {
            int j = tid >> 2, q4 = tid & 3;
            const float4* er = (const float4*)&S->Esh[j][0];
            const float4* vr = (const float4*)S->vB;
            float s = 0.f;
            #pragma unroll
            for (int q = 0; q < 16; q++) {
                float4 e4 = er[q4 + 4 * q], v4 = vr[q4 + 4 * q];
                s += e4.x * v4.x + e4.y * v4.y + e4.z * v4.z + e4.w * v4.w;
            }
            s += __shfl_xor_sync(0xFFFFFFFFu, s, 1);
            s += __shfl_xor_sync(0xFFFFFFFFu, s, 2);
            if (q4 == 0) S->uch[j] = (j < cnt) ? cwv * s : 0.f;
        }
        __syncthreads();
        // ---- scores: thread computes 4i x 4j over its e-half
        ull sc[4][4];
        #pragma unroll
        for (int r = 0; r < 4; r++)
            #pragma unroll
            for (int c = 0; c < 4; c++) sc[r][c] = 0ULL;
        #pragma unroll 4
        for (int e = e0; e < e0 + 128; e += 4) {
            ulonglong2 zr0 = *(const ulonglong2*)&S->zsh[ig * 4 + 0][e];
            ulonglong2 zr1 = *(const ulonglong2*)&S->zsh[ig * 4 + 1][e];
            ulonglong2 zr2 = *(const ulonglong2*)&S->zsh[ig * 4 + 2][e];
            ulonglong2 zr3 = *(const ulonglong2*)&S->zsh[ig * 4 + 3][e];
            ulonglong2 ee0 = *(const ulonglong2*)&S->Esh[jg][e];
            ulonglong2 ee1 = *(const ulonglong2*)&S->Esh[jg + 32][e];
            ulonglong2 ee2 = *(const ulonglong2*)&S->Esh[jg + 64][e];
            ulonglong2 ee3 = *(const ulonglong2*)&S->Esh[jg + 96][e];
            FMA2(sc[0][0], zr0.x, ee0.x); FMA2(sc[0][0], zr0.y, ee0.y);
            FMA2(sc[0][1], zr0.x, ee1.x); FMA2(sc[0][1], zr0.y, ee1.y);
            FMA2(sc[0][2], zr0.x, ee2.x); FMA2(sc[0][2], zr0.y, ee2.y);
            FMA2(sc[0][3], zr0.x, ee3.x); FMA2(sc[0][3], zr0.y, ee3.y);
            FMA2(sc[1][0], zr1.x, ee0.x); FMA2(sc[1][0], zr1.y, ee0.y);
            FMA2(sc[1][1], zr1.x, ee1.x); FMA2(sc[1][1], zr1.y, ee1.y);
            FMA2(sc[1][2], zr1.x, ee2.x); FMA2(sc[1][2], zr1.y, ee2.y);
            FMA2(sc[1][3], zr1.x, ee3.x); FMA2(sc[1][3], zr1.y, ee3.y);
            FMA2(sc[2][0], zr2.x, ee0.x); FMA2(sc[2][0], zr2.y, ee0.y);
            FMA2(sc[2][1], zr2.x, ee1.x); FMA2(sc[2][1], zr2.y, ee1.y);
            FMA2(sc[2][2], zr2.x, ee2.x); FMA2(sc[2][2], zr2.y, ee2.y);
            FMA2(sc[2][3], zr2.x, ee3.x); FMA2(sc[2][3], zr2.y, ee3.y);
            FMA2(sc[3][0], zr3.x, ee0.x); FMA2(sc[3][0], zr3.y, ee0.y);
            FMA2(sc[3][1], zr3.x, ee1.x); FMA2(sc[3][1], zr3.y, ee1.y);
            FMA2(sc[3][2], zr3.x, ee2.x); FMA2(sc[3][2], zr3.y, ee2.y);
            FMA2(sc[3][3], zr3.x, ee3.x); FMA2(sc[3][3], zr3.y, ee3.y);
        }
        // half1 publishes partial sums into ssh[j][i]
        if (eh == 1) {
            #pragma unroll
            for (int r = 0; r < 4; r++)
                #pragma unroll
                for (int c = 0; c < 4; c++) {
                    float2 a = u2f(sc[r][c]);
                    S->ssh[jg + 32 * c][ig * 4 + r] = a.x + a.y;
                }
        }
        __syncthreads();
        // half0 combines, adds bias terms, computes local maxima
        float sv[4][4];
        if (eh == 0) {
            #pragma unroll
            for (int r = 0; r < 4; r++) {
                float lm = -1e30f;
                float vci = S->vch[ig * 4 + r];
                #pragma unroll
                for (int c = 0; c < 4; c++) {
                    int j = jg + 32 * c;
                    float2 a = u2f(sc[r][c]);
                    float s = (a.x + a.y) + S->ssh[j][ig * 4 + r] + vci + S->uch[j];
                    sv[r][c] = (j < cnt) ? s : -1e30f;
                    lm = fmaxf(lm, sv[r][c]);
                }
                S->red[jg][ig * 4 + r] = lm;
            }
        }
        __syncthreads();
        if (tid < 32) {
            float mo = S->m[tid], mn = mo;
            #pragma unroll 8
            for (int g = 0; g < 32; g++) mn = fmaxf(mn, S->red[g][tid]);
            S->scale[tid] = __expf(mo - mn);
            S->m[tid] = mn;
        }
        __syncthreads();
        if (eh == 0) {
            #pragma unroll
            for (int r = 0; r < 4; r++) {
                float mi = S->m[ig * 4 + r];
                float ls = 0.f;
                #pragma unroll
                for (int c = 0; c < 4; c++) {
                    float w = __expf(sv[r][c] - mi);
                    S->ssh[jg + 32 * c][ig * 4 + r] = w;
                    ls += w;
                }
                S->red[jg][ig * 4 + r] = ls;
            }
        }
        __syncthreads();
        if (tid < 32) {
            float cs = 0.f;
            #pragma unroll 8
            for (int g = 0; g < 32; g++) cs += S->red[g][tid];
            S->dsum[tid] = S->dsum[tid] * S->scale[tid] + cs;
        }
        __syncthreads();
        // ---- V accumulate: (eh, dd): i in [ih, ih+16), d = dd
        #pragma unroll
        for (int p = 0; p < 8; p++) {
            ull sp = pack2(S->scale[ih + 2 * p], S->scale[ih + 2 * p + 1]);
            accv[p] = MUL2(accv[p], sp);
        }
        for (int j = 0; j < 128; j++) {
            ull ev2 = splat2(S->Esh[j][dd]);
            ulonglong2 w0 = *(const ulonglong2*)&S->ssh[j][ih];
            ulonglong2 w1 = *(const ulonglong2*)&S->ssh[j][ih + 4];
            ulonglong2 w2 = *(const ulonglong2*)&S->ssh[j][ih + 8];
            ulonglong2 w3 = *(const ulonglong2*)&S->ssh[j][ih + 12];
            FMA2(accv[0], w0.x, ev2); FMA2(accv[1], w0.y, ev2);
            FMA2(accv[2], w1.x, ev2); FMA2(accv[3], w1.y, ev2);
            FMA2(accv[4], w2.x, ev2); FMA2(accv[5], w2.y, ev2);
            FMA2(accv[6], w3.x, ev2); FMA2(accv[7], w3.y, ev2);
        }
    }
    __syncthreads();
    // ---- epilogue: (eh, dd) writes i in [ih, ih+16)
    float sndv = 0.f;
    #pragma unroll
    for (int c = 0; c < 4; c++) sndv += g_partAll[b][c][dd] - g_partDoor[b][c][dd];
    #pragma unroll
    for (int p = 0; p < 8; p++) {
        float2 ap = u2f(accv[p]);
        #pragma unroll
        for (int h = 0; h < 2; h++) {
            int i = ih + 2 * p + h;
            if (i < ni) {
                float av = h ? ap.y : ap.x;
                float em = __expf(-S->m[i]);
                float denom = (float)(NS - nd) * em + S->dsum[i];
                int srow = g_sw_idx[b][i0 + i];
                size_t o = ((size_t)b * NS + srow) * ND + dd;
                out[o] = emb[o] + 0.5f * ((em * sndv + av) / denom);
            }
        }
    }
}

// ---------------- launch: fork-join graph (all forks rejoin at the end) ------
extern "C" void kernel_launch(void* const* d_in, const int* in_sizes, int n_in,
                              void* d_out, int out_size) {
    const float* emb = (const float*)d_in[0];
    const int*   s32 = (const int*)d_in[1];   // int32 or int64, detected per block
    const float* Wq  = (const float*)d_in[2];
    const float* bq  = (const float*)d_in[3];
    const float* Wk  = (const float*)d_in[4];
    const float* bk  = (const float*)d_in[5];
    const float* cw  = (const float*)d_in[6];
    // d_in[7] = causal_bias: cancels inside softmax, unused.
    float* out = (float*)d_out;

    static bool inited = false;
    static cudaStream_t s1, s2;
    static cudaEvent_t eFork, eP, eD;
    if (!inited) {
        cudaStreamCreateWithFlags(&s1, cudaStreamNonBlocking);
        cudaStreamCreateWithFlags(&s2, cudaStreamNonBlocking);
        cudaEventCreateWithFlags(&eFork, cudaEventDisableTiming);
        cudaEventCreateWithFlags(&eP,    cudaEventDisableTiming);
        cudaEventCreateWithFlags(&eD,    cudaEventDisableTiming);
        cudaFuncSetAttribute(k_attn, cudaFuncAttributeMaxDynamicSharedMemorySize,
                             (int)sizeof(AttnSmem));
        inited = true;
    }

    cudaEventRecord(eFork, 0);
    cudaStreamWaitEvent(s1, eFork, 0);
    cudaStreamWaitEvent(s2, eFork, 0);

    // launch 1-2: k_M (main) || k_prep2 (s1)
    k_M<<<65, 256>>>(Wq, Wk, bq, bk);
    k_prep2<<<dim3(NB, 5), 1024, 0, s1>>>(s32, emb);
    cudaEventRecord(eP, s1);

    // launch 3: k_z (main; needs M + masks)
    cudaStreamWaitEvent(0, eP, 0);
    k_z<<<dim3(2, NB, 32), 256>>>(emb, cw);

    // launch 4: k_attn (main; needs M, masks, z, colsums) — ncu profiles this
    k_attn<<<dim3(NS / 32, NB), 512, sizeof(AttnSmem)>>>(emb, out, cw);

    // launch 5: k_default (s2; row-disjoint with k_attn; rejoin at the end)
    cudaStreamWaitEvent(s2, eP, 0);
    k_default<<<(NB * NS * (ND / 4)) / 256, 256, 0, s2>>>(emb, out);
    cudaEventRecord(eD, s2);
    cudaStreamWaitEvent(0, eD, 0);
}

// round 12
// speedup vs baseline: 1.1420x; 1.1420x over previous
#include <cuda_runtime.h>
#include <cuda_bf16.h>

#define NB 32
#define NS 1024
#define ND 256

typedef unsigned long long ull;

// ---------------- packed f32x2 helpers --------------------------------------
__device__ __forceinline__ void FMA2(ull& d, ull a, ull b) {
    asm("fma.rn.f32x2 %0, %1, %2, %0;" : "+l"(d) : "l"(a), "l"(b));
}
__device__ __forceinline__ ull MUL2(ull a, ull b) {
    ull d;
    asm("mul.rn.f32x2 %0, %1, %2;" : "=l"(d) : "l"(a), "l"(b));
    return d;
}
__device__ __forceinline__ ull splat2(float v) {
    ull r;
    asm("mov.b64 %0, {%1, %1};" : "=l"(r) : "f"(v));
    return r;
}
__device__ __forceinline__ ull pack2(float x, float y) {
    ull r;
    asm("mov.b64 %0, {%1, %2};" : "=l"(r) : "f"(x), "f"(y));
    return r;
}
__device__ __forceinline__ float2 u2f(ull v) {
    float2 r;
    asm("mov.b64 {%0, %1}, %2;" : "=f"(r.x), "=f"(r.y) : "l"(v));
    return r;
}

// ---------------- scratch (static __device__, no allocation) ----------------
__device__ __align__(16) float g_M[ND][ND];     // M[d][e] = sum_a Wq[a][d]*Wk[a][e]
__device__ __align__(16) float g_vecA[ND];      // Wq^T bk
__device__ __align__(16) float g_vecB[ND];      // Wk^T bq
__device__ float g_c;                           // bq . bk
__device__ int   g_sw_idx[NB][NS];
__device__ int   g_dr_idx[NB][NS];
__device__ int   g_nsw[NB];
__device__ int   g_ndr[NB];
__device__ int   g_swf[NB * NS];                // 1 iff switch row
__device__ __align__(16) float g_partAll[NB][4][ND];
__device__ __align__(16) float g_partDoor[NB][4][ND];
__device__ __align__(16) float g_z[NB][NS][ND]; // cw*(x_s . M) per switch slot

// ---------------- K_M: M = Wq^T Wk (32x32 tiles) + bias vectors + c ---------
__global__ void __launch_bounds__(256) k_M(const float* __restrict__ Wq,
                                           const float* __restrict__ Wk,
                                           const float* __restrict__ bq,
                                           const float* __restrict__ bk) {
    int tid = threadIdx.x;
    if (blockIdx.x == 64) {
        int d = tid;
        float va = 0.f, vb = 0.f;
        #pragma unroll 8
        for (int a = 0; a < ND; a++) {
            va += Wq[a * ND + d] * bk[a];
            vb += Wk[a * ND + d] * bq[a];
        }
        g_vecA[d] = va;
        g_vecB[d] = vb;
        if (tid < 32) {
            float c = 0.f;
            for (int i = tid; i < ND; i += 32) c += bq[i] * bk[i];
            #pragma unroll
            for (int o = 16; o; o >>= 1) c += __shfl_down_sync(0xFFFFFFFFu, c, o);
            if (tid == 0) g_c = c;
        }
        return;
    }
    int dt = blockIdx.x >> 3, et = blockIdx.x & 7;
    __shared__ float As[16][32], Bs[16][32];
    float a00 = 0.f, a01 = 0.f, a10 = 0.f, a11 = 0.f;
    int dg = tid >> 4, eg = tid & 15;
    int al = tid >> 4, c2 = (tid & 15) * 2;
    for (int a0 = 0; a0 < ND; a0 += 16) {
        *(float2*)&As[al][c2] = *(const float2*)&Wq[(a0 + al) * ND + dt * 32 + c2];
        *(float2*)&Bs[al][c2] = *(const float2*)&Wk[(a0 + al) * ND + et * 32 + c2];
        __syncthreads();
        #pragma unroll
        for (int k = 0; k < 16; k++) {
            float2 av = *(const float2*)&As[k][dg * 2];
            float2 bv = *(const float2*)&Bs[k][eg * 2];
            a00 += av.x * bv.x; a01 += av.x * bv.y;
            a10 += av.y * bv.x; a11 += av.y * bv.y;
        }
        __syncthreads();
    }
    int d = dt * 32 + dg * 2, e = et * 32 + eg * 2;
    g_M[d][e]     = a00; g_M[d][e + 1]     = a01;
    g_M[d + 1][e] = a10; g_M[d + 1][e + 1] = a11;
}

// ---------------- K_prep2: dtype detect + masks/flags (bz0) | colsum --------
__global__ void __launch_bounds__(1024) k_prep2(const int* __restrict__ s32,
                                                const float* __restrict__ emb) {
    int b = blockIdx.x, bz = blockIdx.y, tid = threadIdx.x;
    int vdet = (tid < 512) ? s32[b * NS + 2 * tid + 1] : 0;
    int is64 = !__syncthreads_or(vdet != 0);

    if (bz == 0) {
        int t = tid;
        int st = is64 ? s32[2 * (b * NS + t)] : s32[b * NS + t];
        int isw = (st == 3), idr = (st == 4 || st == 5);
        g_swf[b * NS + t] = isw;
        unsigned mw = __ballot_sync(0xFFFFFFFFu, isw);
        unsigned md = __ballot_sync(0xFFFFFFFFu, idr);
        int lane = t & 31, w = t >> 5;
        __shared__ int cw_[32], cd_[32], ow_[32], od_[32];
        if (lane == 0) { cw_[w] = __popc(mw); cd_[w] = __popc(md); }
        __syncthreads();
        if (tid == 0) {
            int aw = 0, ad = 0;
            for (int i = 0; i < 32; i++) {
                ow_[i] = aw; aw += cw_[i];
                od_[i] = ad; ad += cd_[i];
            }
            g_nsw[b] = aw; g_ndr[b] = ad;
        }
        __syncthreads();
        if (isw) g_sw_idx[b][ow_[w] + __popc(mw & ((1u << lane) - 1u))] = t;
        if (idr) g_dr_idx[b][od_[w] + __popc(md & ((1u << lane) - 1u))] = t;
    } else {
        int c = bz - 1, tg = tid >> 8, d = tid & 255;
        float sa = 0.f, sd = 0.f;
        int tb = c * 256 + tg * 64;
        #pragma unroll 4
        for (int i = 0; i < 64; i++) {
            int t = tb + i;
            float v = emb[((size_t)b * NS + t) * ND + d];
            int st = is64 ? s32[2 * (b * NS + t)] : s32[b * NS + t];
            sa += v;
            if (st == 4 || st == 5) sd += v;
        }
        __shared__ float psA[4][ND], psD[4][ND];
        psA[tg][d] = sa; psD[tg][d] = sd;
        __syncthreads();
        if (tid < ND) {
            float a = 0.f, dd = 0.f;
            #pragma unroll
            for (int g = 0; g < 4; g++) { a += psA[g][tid]; dd += psD[g][tid]; }
            g_partAll[b][c][tid]  = a;
            g_partDoor[b][c][tid] = dd;
        }
    }
}

// ---------------- K_default: out = emb + 0.5*colMean (non-switch rows only) -
__global__ void __launch_bounds__(256) k_default(const float* __restrict__ emb,
                                                 float* __restrict__ out) {
    size_t e4 = (size_t)blockIdx.x * 256 + threadIdx.x;
    int row = (int)(e4 >> 6);               // b*NS + s
    if (g_swf[row]) return;                  // switch rows owned by k_attn
    int b  = (int)(e4 >> 16);
    int d4 = (int)(e4 & 63);
    float4 p0 = ((const float4*)g_partAll[b][0])[d4];
    float4 p1 = ((const float4*)g_partAll[b][1])[d4];
    float4 p2 = ((const float4*)g_partAll[b][2])[d4];
    float4 p3 = ((const float4*)g_partAll[b][3])[d4];
    const float kk = 0.5f / 1024.f;
    float4 v = ((const float4*)emb)[e4];
    v.x += (p0.x + p1.x + p2.x + p3.x) * kk;
    v.y += (p0.y + p1.y + p2.y + p3.y) * kk;
    v.z += (p0.z + p1.z + p2.z + p3.z) * kk;
    v.w += (p0.w + p1.w + p2.w + p3.w) * kk;
    ((float4*)out)[e4] = v;
}

// ---------------- K_z: z = cw * X_switch . M, 64x128 reg tiles (R10 best) ---
__global__ void __launch_bounds__(256) k_z(const float* __restrict__ emb,
                                           const float* __restrict__ cwp) {
    int et = blockIdx.x, b = blockIdx.y, mt = blockIdx.z;
    int nsw = g_nsw[b];
    if (mt * 64 >= nsw) return;
    int tid = threadIdx.x;
    __shared__ float Xs[2][16][68];
    __shared__ float Ms[2][16][132];
    __shared__ const float* rp[64];
    if (tid < 64) {
        int slot = mt * 64 + tid;
        rp[tid] = emb + ((size_t)b * NS + g_sw_idx[b][min(slot, nsw - 1)]) * ND;
    }
    __syncthreads();
    const int xrow = tid >> 2, xk4 = (tid & 3) * 4;
    const int mkr = tid >> 5,  me4 = (tid & 31) * 4;
    const int rg = tid >> 4, eg = tid & 15;
    const float* xp = rp[xrow];
    const float* mp = &g_M[0][et * 128 + me4];

    float4 xv = *(const float4*)(xp + xk4);
    float4 ma = *(const float4*)(mp + (size_t)mkr * ND);
    float4 mb = *(const float4*)(mp + (size_t)(mkr + 8) * ND);
    Xs[0][xk4 + 0][xrow] = xv.x; Xs[0][xk4 + 1][xrow] = xv.y;
    Xs[0][xk4 + 2][xrow] = xv.z; Xs[0][xk4 + 3][xrow] = xv.w;
    *(float4*)&Ms[0][mkr][me4]     = ma;
    *(float4*)&Ms[0][mkr + 8][me4] = mb;
    __syncthreads();

    ull acc[4][4];
    #pragma unroll
    for (int r = 0; r < 4; r++)
        #pragma unroll
        for (int p = 0; p < 4; p++) acc[r][p] = 0ULL;

    for (int s = 0; s < 16; s++) {
        int cur = s & 1;
        if (s + 1 < 16) {
            int k0 = (s + 1) * 16;
            xv = *(const float4*)(xp + k0 + xk4);
            ma = *(const float4*)(mp + (size_t)(k0 + mkr) * ND);
            mb = *(const float4*)(mp + (size_t)(k0 + mkr + 8) * ND);
        }
        #pragma unroll
        for (int k = 0; k < 16; k++) {
            float4 xf = *(const float4*)&Xs[cur][k][rg * 4];
            ulonglong2 m0 = *(const ulonglong2*)&Ms[cur][k][eg * 8];
            ulonglong2 m1 = *(const ulonglong2*)&Ms[cur][k][eg * 8 + 4];
            ull x0 = splat2(xf.x), x1 = splat2(xf.y);
            ull x2 = splat2(xf.z), x3 = splat2(xf.w);
            FMA2(acc[0][0], x0, m0.x); FMA2(acc[0][1], x0, m0.y);
            FMA2(acc[0][2], x0, m1.x); FMA2(acc[0][3], x0, m1.y);
            FMA2(acc[1][0], x1, m0.x); FMA2(acc[1][1], x1, m0.y);
            FMA2(acc[1][2], x1, m1.x); FMA2(acc[1][3], x1, m1.y);
            FMA2(acc[2][0], x2, m0.x); FMA2(acc[2][1], x2, m0.y);
            FMA2(acc[2][2], x2, m1.x); FMA2(acc[2][3], x2, m1.y);
            FMA2(acc[3][0], x3, m0.x); FMA2(acc[3][1], x3, m0.y);
            FMA2(acc[3][2], x3, m1.x); FMA2(acc[3][3], x3, m1.y);
        }
        if (s + 1 < 16) {
            int nb2 = cur ^ 1;
            Xs[nb2][xk4 + 0][xrow] = xv.x; Xs[nb2][xk4 + 1][xrow] = xv.y;
            Xs[nb2][xk4 + 2][xrow] = xv.z; Xs[nb2][xk4 + 3][xrow] = xv.w;
            *(float4*)&Ms[nb2][mkr][me4]     = ma;
            *(float4*)&Ms[nb2][mkr + 8][me4] = mb;
            __syncthreads();
        }
    }
    float cwv = *cwp;
    #pragma unroll
    for (int r = 0; r < 4; r++) {
        int slot = mt * 64 + rg * 4 + r;
        if (slot < nsw) {
            float2 a0 = u2f(acc[r][0]), a1 = u2f(acc[r][1]);
            float2 a2 = u2f(acc[r][2]), a3 = u2f(acc[r][3]);
            float4 o0 = make_float4(cwv * a0.x, cwv * a0.y, cwv * a1.x, cwv * a1.y);
            float4 o1 = make_float4(cwv * a2.x, cwv * a2.y, cwv * a3.x, cwv * a3.y);
            *(float4*)&g_z[b][slot][et * 128 + eg * 8]     = o0;
            *(float4*)&g_z[b][slot][et * 128 + eg * 8 + 4] = o1;
        }
    }
}

// ---------------- K_attn: fused, 512 thr, 32i x 128j, K-split score GEMM ----
struct AttnSmem {
    float Esh[128][260];   // door-row emb tile (pad: phase-conflict-free)
    float zsh[32][260];    // z rows for this i-tile
    float ssh[128][36];    // half1 partial scores -> softmax weights [j][i]
    float red[32][36];     // per-jg partial max/sum [jg][i]
    float uch[128];
    int   tj[128];
    float vch[32];
    float m[32];
    float dsum[32];
    float scale[32];
    float vA[ND];
    float vB[ND];
};

__global__ void __launch_bounds__(512) k_attn(const float* __restrict__ emb,
                                              float* __restrict__ out,
                                              const float* __restrict__ cwp) {
    extern __shared__ char smraw[];
    AttnSmem* S = (AttnSmem*)smraw;
    const int mt = blockIdx.x, b = blockIdx.y;
    const int nsw = g_nsw[b];
    const int i0 = mt * 32;
    if (i0 >= nsw) return;
    const int nd = g_ndr[b];
    const int tid = threadIdx.x;
    const int ni = min(32, nsw - i0);
    const float cwv = *cwp;

    // ---- prologue: z tile, bias vectors, m/dsum, vc
    for (int idx = tid; idx < 32 * 64; idx += 512) {
        int i = idx >> 6, q = idx & 63;
        float4 v = (i < ni) ? ((const float4*)&g_z[b][i0 + i][0])[q]
                            : make_float4(0.f, 0.f, 0.f, 0.f);
        *(float4*)&S->zsh[i][q * 4] = v;
    }
    if (tid < ND) { S->vA[tid] = g_vecA[tid]; S->vB[tid] = g_vecB[tid]; }
    if (tid < 32) {
        S->m[tid]    = (nd < NS) ? 0.f : -1e30f;
        S->dsum[tid] = 0.f;
    }
    {   // vc: warp w (0..15) covers rows w, w+16
        int w = tid >> 5, lane = tid & 31;
        for (int r = w; r < 32; r += 16) {
            float val = -1e30f;
            if (r < ni) {
                int srow = g_sw_idx[b][i0 + r];
                const float4* er = (const float4*)&emb[((size_t)b * NS + srow) * ND];
                const float4* vr = (const float4*)g_vecA;
                float s = 0.f;
                #pragma unroll
                for (int j2 = 0; j2 < 2; j2++) {
                    float4 e4 = er[lane + 32 * j2], v4 = vr[lane + 32 * j2];
                    s += e4.x * v4.x + e4.y * v4.y + e4.z * v4.z + e4.w * v4.w;
                }
                #pragma unroll
                for (int o = 16; o; o >>= 1) s += __shfl_down_sync(0xFFFFFFFFu, s, o);
                val = cwv * (s + g_c);
            }
            if (lane == 0) S->vch[r] = val;
        }
    }

    const int eh = tid >> 8;         // 0/1: e-half (scores), i-half (V)
    const int t8 = tid & 255;
    const int ig = t8 >> 5;          // 0..7  -> i = ig*4 + r
    const int jg = t8 & 31;          // 0..31 -> j = jg + 32*c
    const int e0 = eh * 128;
    const int ih = eh * 16;          // V-phase i-half base
    const int dd = t8;               // V-phase d index

    ull accv[8];
    #pragma unroll
    for (int p = 0; p < 8; p++) accv[p] = 0ULL;

    for (int jb = 0; jb < nd; jb += 128) {
        int cnt = min(128, nd - jb);
        __syncthreads();
        if (tid < 128)
            S->tj[tid] = g_dr_idx[b][(tid < cnt) ? (jb + tid) : jb];
        __syncthreads();
        for (int idx = tid; idx < 128 * 64; idx += 512) {
            int j = idx >> 6, q = idx & 63;
            float4 v = ((const float4*)&emb[((size_t)b * NS + S->tj[j]) * ND])[q];
            *(float4*)&S->Esh[j][q * 4] = v;
        }
        __syncthreads();
        // ---- uc_j = cw * (E_j . vecB): 4 threads per j
        {
            int j = tid >> 2, q4 = tid & 3;
            const float4* er = (const float4*)&S->Esh[j][0];
            const float4* vr = (const float4*)S->vB;
            float s = 0.f;
            #pragma unroll
            for (int q = 0; q < 16; q++) {
                float4 e4 = er[q4 + 4 * q], v4 = vr[q4 + 4 * q];
                s += e4.x * v4.x + e4.y * v4.y + e4.z * v4.z + e4.w * v4.w;
            }
            s += __shfl_xor_sync(0xFFFFFFFFu, s, 1);
            s += __shfl_xor_sync(0xFFFFFFFFu, s, 2);
            if (q4 == 0) S->uch[j] = (j < cnt) ? cwv * s : 0.f;
        }
        __syncthreads();
        // ---- scores: thread computes 4i x 4j over its e-half
        ull sc[4][4];
        #pragma unroll
        for (int r = 0; r < 4; r++)
            #pragma unroll
            for (int c = 0; c < 4; c++) sc[r][c] = 0ULL;
        #pragma unroll 4
        for (int e = e0; e < e0 + 128; e += 4) {
            ulonglong2 zr0 = *(const ulonglong2*)&S->zsh[ig * 4 + 0][e];
            ulonglong2 zr1 = *(const ulonglong2*)&S->zsh[ig * 4 + 1][e];
            ulonglong2 zr2 = *(const ulonglong2*)&S->zsh[ig * 4 + 2][e];
            ulonglong2 zr3 = *(const ulonglong2*)&S->zsh[ig * 4 + 3][e];
            ulonglong2 ee0 = *(const ulonglong2*)&S->Esh[jg][e];
            ulonglong2 ee1 = *(const ulonglong2*)&S->Esh[jg + 32][e];
            ulonglong2 ee2 = *(const ulonglong2*)&S->Esh[jg + 64][e];
            ulonglong2 ee3 = *(const ulonglong2*)&S->Esh[jg + 96][e];
            FMA2(sc[0][0], zr0.x, ee0.x); FMA2(sc[0][0], zr0.y, ee0.y);
            FMA2(sc[0][1], zr0.x, ee1.x); FMA2(sc[0][1], zr0.y, ee1.y);
            FMA2(sc[0][2], zr0.x, ee2.x); FMA2(sc[0][2], zr0.y, ee2.y);
            FMA2(sc[0][3], zr0.x, ee3.x); FMA2(sc[0][3], zr0.y, ee3.y);
            FMA2(sc[1][0], zr1.x, ee0.x); FMA2(sc[1][0], zr1.y, ee0.y);
            FMA2(sc[1][1], zr1.x, ee1.x); FMA2(sc[1][1], zr1.y, ee1.y);
            FMA2(sc[1][2], zr1.x, ee2.x); FMA2(sc[1][2], zr1.y, ee2.y);
            FMA2(sc[1][3], zr1.x, ee3.x); FMA2(sc[1][3], zr1.y, ee3.y);
            FMA2(sc[2][0], zr2.x, ee0.x); FMA2(sc[2][0], zr2.y, ee0.y);
            FMA2(sc[2][1], zr2.x, ee1.x); FMA2(sc[2][1], zr2.y, ee1.y);
            FMA2(sc[2][2], zr2.x, ee2.x); FMA2(sc[2][2], zr2.y, ee2.y);
            FMA2(sc[2][3], zr2.x, ee3.x); FMA2(sc[2][3], zr2.y, ee3.y);
            FMA2(sc[3][0], zr3.x, ee0.x); FMA2(sc[3][0], zr3.y, ee0.y);
            FMA2(sc[3][1], zr3.x, ee1.x); FMA2(sc[3][1], zr3.y, ee1.y);
            FMA2(sc[3][2], zr3.x, ee2.x); FMA2(sc[3][2], zr3.y, ee2.y);
            FMA2(sc[3][3], zr3.x, ee3.x); FMA2(sc[3][3], zr3.y, ee3.y);
        }
        // half1 publishes partial sums into ssh[j][i]
        if (eh == 1) {
            #pragma unroll
            for (int r = 0; r < 4; r++)
                #pragma unroll
                for (int c = 0; c < 4; c++) {
                    float2 a = u2f(sc[r][c]);
                    S->ssh[jg + 32 * c][ig * 4 + r] = a.x + a.y;
                }
        }
        __syncthreads();
        // half0 combines, adds bias terms, computes local maxima
        float sv[4][4];
        if (eh == 0) {
            #pragma unroll
            for (int r = 0; r < 4; r++) {
                float lm = -1e30f;
                float vci = S->vch[ig * 4 + r];
                #pragma unroll
                for (int c = 0; c < 4; c++) {
                    int j = jg + 32 * c;
                    float2 a = u2f(sc[r][c]);
                    float s = (a.x + a.y) + S->ssh[j][ig * 4 + r] + vci + S->uch[j];
                    sv[r][c] = (j < cnt) ? s : -1e30f;
                    lm = fmaxf(lm, sv[r][c]);
                }
                S->red[jg][ig * 4 + r] = lm;
            }
        }
        __syncthreads();
        if (tid < 32) {
            float mo = S->m[tid], mn = mo;
            #pragma unroll 8
            for (int g = 0; g < 32; g++) mn = fmaxf(mn, S->red[g][tid]);
            S->scale[tid] = __expf(mo - mn);
            S->m[tid] = mn;
        }
        __syncthreads();
        if (eh == 0) {
            #pragma unroll
            for (int r = 0; r < 4; r++) {
                float mi = S->m[ig * 4 + r];
                float ls = 0.f;
                #pragma unroll
                for (int c = 0; c < 4; c++) {
                    float w = __expf(sv[r][c] - mi);
                    S->ssh[jg + 32 * c][ig * 4 + r] = w;
                    ls += w;
                }
                S->red[jg][ig * 4 + r] = ls;
            }
        }
        __syncthreads();
        if (tid < 32) {
            float cs = 0.f;
            #pragma unroll 8
            for (int g = 0; g < 32; g++) cs += S->red[g][tid];
            S->dsum[tid] = S->dsum[tid] * S->scale[tid] + cs;
        }
        __syncthreads();
        // ---- V accumulate: (eh, dd): i in [ih, ih+16), d = dd
        #pragma unroll
        for (int p = 0; p < 8; p++) {
            ull sp = pack2(S->scale[ih + 2 * p], S->scale[ih + 2 * p + 1]);
            accv[p] = MUL2(accv[p], sp);
        }
        for (int j = 0; j < 128; j++) {
            ull ev2 = splat2(S->Esh[j][dd]);
            ulonglong2 w0 = *(const ulonglong2*)&S->ssh[j][ih];
            ulonglong2 w1 = *(const ulonglong2*)&S->ssh[j][ih + 4];
            ulonglong2 w2 = *(const ulonglong2*)&S->ssh[j][ih + 8];
            ulonglong2 w3 = *(const ulonglong2*)&S->ssh[j][ih + 12];
            FMA2(accv[0], w0.x, ev2); FMA2(accv[1], w0.y, ev2);
            FMA2(accv[2], w1.x, ev2); FMA2(accv[3], w1.y, ev2);
            FMA2(accv[4], w2.x, ev2); FMA2(accv[5], w2.y, ev2);
            FMA2(accv[6], w3.x, ev2); FMA2(accv[7], w3.y, ev2);
        }
    }
    __syncthreads();
    // ---- epilogue: (eh, dd) writes i in [ih, ih+16)
    float sndv = 0.f;
    #pragma unroll
    for (int c = 0; c < 4; c++) sndv += g_partAll[b][c][dd] - g_partDoor[b][c][dd];
    #pragma unroll
    for (int p = 0; p < 8; p++) {
        float2 ap = u2f(accv[p]);
        #pragma unroll
        for (int h = 0; h < 2; h++) {
            int i = ih + 2 * p + h;
            if (i < ni) {
                float av = h ? ap.y : ap.x;
                float em = __expf(-S->m[i]);
                float denom = (float)(NS - nd) * em + S->dsum[i];
                int srow = g_sw_idx[b][i0 + i];
                size_t o = ((size_t)b * NS + srow) * ND + dd;
                out[o] = emb[o] + 0.5f * ((em * sndv + av) / denom);
            }
        }
    }
}

// ---------------- launch: fork-join graph (all forks rejoin at the end) ------
extern "C" void kernel_launch(void* const* d_in, const int* in_sizes, int n_in,
                              void* d_out, int out_size) {
    const float* emb = (const float*)d_in[0];
    const int*   s32 = (const int*)d_in[1];   // int32 or int64, detected per block
    const float* Wq  = (const float*)d_in[2];
    const float* bq  = (const float*)d_in[3];
    const float* Wk  = (const float*)d_in[4];
    const float* bk  = (const float*)d_in[5];
    const float* cw  = (const float*)d_in[6];
    // d_in[7] = causal_bias: cancels inside softmax, unused.
    float* out = (float*)d_out;

    static bool inited = false;
    static cudaStream_t s1, s2;
    static cudaEvent_t eFork, eP, eD;
    if (!inited) {
        cudaStreamCreateWithFlags(&s1, cudaStreamNonBlocking);
        cudaStreamCreateWithFlags(&s2, cudaStreamNonBlocking);
        cudaEventCreateWithFlags(&eFork, cudaEventDisableTiming);
        cudaEventCreateWithFlags(&eP,    cudaEventDisableTiming);
        cudaEventCreateWithFlags(&eD,    cudaEventDisableTiming);
        cudaFuncSetAttribute(k_attn, cudaFuncAttributeMaxDynamicSharedMemorySize,
                             (int)sizeof(AttnSmem));
        inited = true;
    }

    cudaEventRecord(eFork, 0);
    cudaStreamWaitEvent(s1, eFork, 0);
    cudaStreamWaitEvent(s2, eFork, 0);

    // launch 1-2: k_M (main) || k_prep2 (s1)
    k_M<<<65, 256>>>(Wq, Wk, bq, bk);
    k_prep2<<<dim3(NB, 5), 1024, 0, s1>>>(s32, emb);
    cudaEventRecord(eP, s1);

    // launch 3: k_z (main; needs M + masks) — 64-row tiles (measured best)
    cudaStreamWaitEvent(0, eP, 0);
    k_z<<<dim3(2, NB, 16), 256>>>(emb, cw);

    // launch 4: k_attn (main; needs M, masks, z, colsums) — ncu profiles this
    k_attn<<<dim3(NS / 32, NB), 512, sizeof(AttnSmem)>>>(emb, out, cw);

    // launch 5: k_default (s2; row-disjoint with k_attn; rejoin at the end)
    cudaStreamWaitEvent(s2, eP, 0);
    k_default<<<(NB * NS * (ND / 4)) / 256, 256, 0, s2>>>(emb, out);
    cudaEventRecord(eD, s2);
    cudaStreamWaitEvent(0, eD, 0);
}